// round 12
// baseline (speedup 1.0000x reference)
#include <cuda_runtime.h>
#include <cuda_fp16.h>

#define N_NODES 50000
#define N_EDGES 800000
#define NF 64
#define NG 64
#define NC 10
#define NBLK 196   // ceil(50000/256)
#define FIXSCALE 16777216.0f   // 2^24 fixed-point for packed degree

// ---- scratch (static __device__, no runtime allocation) ----
__device__ unsigned long long g_deg64[N_NODES];   // high32: count, low32: sum(w)*2^24
__device__ float g_dis[N_NODES];
__device__ int   g_off[N_NODES + 1];
__device__ int   g_cur[N_NODES];
__device__ int   g_bsum[256];
__device__ __align__(16) int2 g_edge[N_EDGES];     // (src_row, dis[src]*w as bits)
__device__ __align__(256) __half g_Ah[N_NODES * NF];  // fp16 gemm out (gathered)
__device__ __align__(256) float  g_B[N_NODES * NF];   // fp32 agg out
__device__ float g_pool[NG * NF];
__device__ float g_gcnt[NG];

// ---------------------------------------------------------------------------
__global__ void k_init() {
    int i = blockIdx.x * blockDim.x + threadIdx.x;
    if (i < N_NODES) g_deg64[i] = 0ull;
    if (i < NG * NF) g_pool[i] = 0.0f;
    if (i < NG)      g_gcnt[i] = 0.0f;
    if (i == 0)      g_off[N_NODES] = N_EDGES;             // total is constant
}

// degree + count in ONE packed 64-bit atomic per edge
__global__ void k_deg(const int* __restrict__ col, const float* __restrict__ P) {
    int e = blockIdx.x * blockDim.x + threadIdx.x;
    if (e >= N_EDGES) return;
    float w = 1.0f / (1.0f + expf(-P[e]));
    unsigned long long pk = (1ull << 32) |
        (unsigned long long)(unsigned int)__float2uint_rn(w * FIXSCALE);
    atomicAdd(&g_deg64[col[e]], pk);
}

// ---- scan phase 1: per-block local exclusive scan of in-degree counts ----
__global__ void k_scan1() {
    __shared__ int s[256];
    int t = threadIdx.x;
    int i = blockIdx.x * 256 + t;
    int v = (i < N_NODES) ? (int)(g_deg64[i] >> 32) : 0;
    int val = v;
    s[t] = val;
    __syncthreads();
    #pragma unroll
    for (int d = 1; d < 256; d <<= 1) {
        int add = (t >= d) ? s[t - d] : 0;
        __syncthreads();
        val += add;
        s[t] = val;
        __syncthreads();
    }
    if (i < N_NODES) g_off[i] = val - v;    // local exclusive
    if (t == 255)    g_bsum[blockIdx.x] = val;
}

// ---- scan phase 2 (fused): each block reduces bsum[0..bid) itself, then
// adds the base to its 256 offsets and computes dis=rsqrt(deg). ----
__global__ void k_scan3() {
    __shared__ int s[256];
    int t = threadIdx.x;
    int bid = blockIdx.x;
    s[t] = (t < bid) ? g_bsum[t] : 0;       // bid <= 195 < 256
    __syncthreads();
    #pragma unroll
    for (int d = 128; d > 0; d >>= 1) {
        if (t < d) s[t] += s[t + d];
        __syncthreads();
    }
    int base = s[0];
    int i = bid * 256 + t;
    if (i >= N_NODES) return;
    int o = g_off[i] + base;
    g_off[i] = o;
    g_cur[i] = o;
    float wsum = (float)(unsigned int)g_deg64[i] * (1.0f / FIXSCALE);
    g_dis[i] = rsqrtf(1.0f + wsum);         // self-loop weight 1 folded in
}

// fill CSC: per incoming edge store (source row, dis[src]*w).
// dis[col] is factored out and applied once per node in k_agg.
__global__ void k_fill(const int* __restrict__ row, const int* __restrict__ col,
                       const float* __restrict__ P) {
    int e = blockIdx.x * blockDim.x + threadIdx.x;
    if (e >= N_EDGES) return;
    int r = row[e], c = col[e];
    float w  = 1.0f / (1.0f + expf(-P[e]));
    float nm = g_dis[r] * w;                // only ONE random gather
    int slot = atomicAdd(&g_cur[c], 1);
    g_edge[slot] = make_int2(r, __float_as_int(nm));
}

// out[n,64] = half(in[n,64] @ W[64,64]); W column register-resident
__global__ void k_gemm(const float* __restrict__ in, const float* __restrict__ W,
                       __half* __restrict__ out) {
    __shared__ float Is[4][64];
    int tx = threadIdx.x & 63;
    int ty = threadIdx.x >> 6;
    float w[64];
    #pragma unroll
    for (int k = 0; k < 64; k++) w[k] = __ldg(&W[k * 64 + tx]);
    int base = blockIdx.x * 64;
    for (int rg = 0; rg < 16; rg++) {
        int r = base + rg * 4 + ty;
        float v = (r < N_NODES) ? in[r * 64 + tx] : 0.0f;
        __syncthreads();
        Is[ty][tx] = v;
        __syncthreads();
        float a0 = 0.f, a1 = 0.f, a2 = 0.f, a3 = 0.f;
        #pragma unroll
        for (int k = 0; k < 64; k += 4) {
            float4 iv = *(const float4*)&Is[ty][k];
            a0 = fmaf(iv.x, w[k],     a0);
            a1 = fmaf(iv.y, w[k + 1], a1);
            a2 = fmaf(iv.z, w[k + 2], a2);
            a3 = fmaf(iv.w, w[k + 3], a3);
        }
        if (r < N_NODES) out[r * 64 + tx] = __float2half_rn((a0 + a1) + (a2 + a3));
    }
}

// warp-per-node gather SpMM, fp16 rows (128B) + SOFTWARE PIPELINE:
// each half-warp owns one edge of a pair; lane f in [0,16) loads uint2 =
// 4 halves (features 4f..4f+3). Next edge batch is prefetched while the
// current gathers are in flight. fp32 accumulation throughout.
// B[c] = dis_c * ( dis_c*h_c + sum_e (dis_r*w_e)*h_r ) + bias
__global__ void __launch_bounds__(256) k_agg(
        const __half* __restrict__ A, float* __restrict__ B,
        const float* __restrict__ bias, int do_relu) {
    int node = blockIdx.x * 8 + (threadIdx.x >> 5);
    if (node >= N_NODES) return;
    int lane = threadIdx.x & 31;
    int half = lane >> 4;                 // 0 or 1: which edge of the pair
    int f    = lane & 15;                 // uint2 index within the 128B row
    const uint2* __restrict__ Ar = (const uint2*)A;

    float dc = g_dis[node];
    // self term: both halves add 0.5*dc*h_self (exact; halves summed later)
    uint2 us = __ldg(&Ar[node * 16 + f]);
    float2 s0 = __half22float2(*(const __half2*)&us.x);
    float2 s1 = __half22float2(*(const __half2*)&us.y);
    float hsc = 0.5f * dc;
    float ax = hsc * s0.x, ay = hsc * s0.y, az = hsc * s1.x, aw = hsc * s1.y;

    int s = g_off[node], e = g_off[node + 1];
    int i = s;
    int2 e0 = make_int2(node, 0), e1 = e0, e2 = e0, e3 = e0;
    bool have = (i + 8 <= e);
    if (have) {
        e0 = g_edge[i     + half];
        e1 = g_edge[i + 2 + half];
        e2 = g_edge[i + 4 + half];
        e3 = g_edge[i + 6 + half];
    }
    while (have) {
        // issue 4 gathers for current edge batch
        uint2 u0 = __ldg(&Ar[e0.x * 16 + f]);
        uint2 u1 = __ldg(&Ar[e1.x * 16 + f]);
        uint2 u2 = __ldg(&Ar[e2.x * 16 + f]);
        uint2 u3 = __ldg(&Ar[e3.x * 16 + f]);
        float n0 = __int_as_float(e0.y), n1 = __int_as_float(e1.y);
        float n2 = __int_as_float(e2.y), n3 = __int_as_float(e3.y);
        // prefetch next edge batch while gathers are outstanding
        i += 8;
        have = (i + 8 <= e);
        int2 p0 = e0, p1 = e1, p2 = e2, p3 = e3;
        if (have) {
            p0 = g_edge[i     + half];
            p1 = g_edge[i + 2 + half];
            p2 = g_edge[i + 4 + half];
            p3 = g_edge[i + 6 + half];
        }
        float2 a0 = __half22float2(*(const __half2*)&u0.x);
        float2 b0 = __half22float2(*(const __half2*)&u0.y);
        float2 a1 = __half22float2(*(const __half2*)&u1.x);
        float2 b1 = __half22float2(*(const __half2*)&u1.y);
        float2 a2 = __half22float2(*(const __half2*)&u2.x);
        float2 b2 = __half22float2(*(const __half2*)&u2.y);
        float2 a3 = __half22float2(*(const __half2*)&u3.x);
        float2 b3 = __half22float2(*(const __half2*)&u3.y);
        ax += n0 * a0.x + n1 * a1.x + n2 * a2.x + n3 * a3.x;
        ay += n0 * a0.y + n1 * a1.y + n2 * a2.y + n3 * a3.y;
        az += n0 * b0.x + n1 * b1.x + n2 * b2.x + n3 * b3.x;
        aw += n0 * b0.y + n1 * b1.y + n2 * b2.y + n3 * b3.y;
        e0 = p0; e1 = p1; e2 = p2; e3 = p3;
    }
    for (; i < e; i += 2) {               // pairwise tail; idle half contributes 0
        int idx = i + half;
        int2 ed = (idx < e) ? g_edge[idx] : make_int2(node, 0);
        uint2 u = __ldg(&Ar[ed.x * 16 + f]);
        float nm = __int_as_float(ed.y);
        float2 a = __half22float2(*(const __half2*)&u.x);
        float2 b = __half22float2(*(const __half2*)&u.y);
        ax += nm * a.x; ay += nm * a.y; az += nm * b.x; aw += nm * b.y;
    }
    // merge the two halves (feature slices identical across halves)
    ax += __shfl_xor_sync(0xffffffffu, ax, 16);
    ay += __shfl_xor_sync(0xffffffffu, ay, 16);
    az += __shfl_xor_sync(0xffffffffu, az, 16);
    aw += __shfl_xor_sync(0xffffffffu, aw, 16);
    if (half == 0) {
        float4 bb = ((const float4*)bias)[f];
        float4 o;
        o.x = dc * ax + bb.x;
        o.y = dc * ay + bb.y;
        o.z = dc * az + bb.z;
        o.w = dc * aw + bb.w;
        if (do_relu) {
            o.x = fmaxf(o.x, 0.0f); o.y = fmaxf(o.y, 0.0f);
            o.z = fmaxf(o.z, 0.0f); o.w = fmaxf(o.w, 0.0f);
        }
        ((float4*)B)[node * 16 + f] = o;
    }
}

// segment mean pool: sorted batch run-length accumulate.
// 256 threads = 16 groups x 16 float4-lanes; each group owns a 32-node chunk.
__global__ void k_pool(const float* __restrict__ B, const int* __restrict__ batch) {
    int t = threadIdx.x;
    int grp = t >> 4;                      // 0..15
    int f   = t & 15;                      // float4 lane
    int start = blockIdx.x * 512 + grp * 32;
    if (start >= N_NODES) return;
    int end = min(start + 32, N_NODES);
    const float4* __restrict__ Br = (const float4*)B;
    int cur = batch[start];
    float4 acc = make_float4(0.f, 0.f, 0.f, 0.f);
    float c = 0.0f;
    for (int i = start; i < end; i++) {
        int g = batch[i];
        if (g != cur) {
            float* p = &g_pool[cur * 64 + f * 4];
            atomicAdd(p + 0, acc.x); atomicAdd(p + 1, acc.y);
            atomicAdd(p + 2, acc.z); atomicAdd(p + 3, acc.w);
            if (f == 0) atomicAdd(&g_gcnt[cur], c);
            acc = make_float4(0.f, 0.f, 0.f, 0.f); c = 0.0f; cur = g;
        }
        float4 v = Br[i * 16 + f];
        acc.x += v.x; acc.y += v.y; acc.z += v.z; acc.w += v.w;
        c += 1.0f;
    }
    float* p = &g_pool[cur * 64 + f * 4];
    atomicAdd(p + 0, acc.x); atomicAdd(p + 1, acc.y);
    atomicAdd(p + 2, acc.z); atomicAdd(p + 3, acc.w);
    if (f == 0) atomicAdd(&g_gcnt[cur], c);
}

// (sums/cnt) @ Wl + bl  -> out[64,10]
__global__ void k_final(const float* __restrict__ Wl, const float* __restrict__ bl,
                        float* __restrict__ out) {
    int t = threadIdx.x;
    if (t >= NG * NC) return;
    int g = t / NC, c = t % NC;
    float cnt = fmaxf(g_gcnt[g], 1.0f);
    float s = 0.0f;
    #pragma unroll
    for (int k = 0; k < 64; k++)
        s += g_pool[g * 64 + k] * Wl[k * NC + c];
    out[t] = s / cnt + bl[c];
}

// ---------------------------------------------------------------------------
extern "C" void kernel_launch(void* const* d_in, const int* in_sizes, int n_in,
                              void* d_out, int out_size) {
    const float* x     = (const float*)d_in[0];
    const int*   ei    = (const int*)  d_in[1];   // [2, E]
    const int*   batch = (const int*)  d_in[2];
    const float* P     = (const float*)d_in[3];
    const float* W1 = (const float*)d_in[4];  const float* b1 = (const float*)d_in[5];
    const float* W2 = (const float*)d_in[6];  const float* b2 = (const float*)d_in[7];
    const float* W3 = (const float*)d_in[8];  const float* b3 = (const float*)d_in[9];
    const float* Wl = (const float*)d_in[10]; const float* bl = (const float*)d_in[11];
    const int* row = ei;
    const int* col = ei + N_EDGES;

    __half* Ah;
    float*  Bv;
    cudaGetSymbolAddress((void**)&Ah, g_Ah);
    cudaGetSymbolAddress((void**)&Bv, g_B);

    const int nb_e = (N_EDGES + 255) / 256;
    const int nb_g = (N_NODES + 63) / 64;
    const int nb_a = (N_NODES + 7) / 8;

    k_init <<<NBLK, 256>>>();
    k_deg  <<<nb_e, 256>>>(col, P);
    k_scan1<<<NBLK, 256>>>();
    k_scan3<<<NBLK, 256>>>();              // fused scan2+scan3
    k_fill <<<nb_e, 256>>>(row, col, P);

    k_gemm<<<nb_g, 256>>>(x,  W1, Ah);
    k_agg <<<nb_a, 256>>>(Ah, Bv, b1, 1);
    k_gemm<<<nb_g, 256>>>(Bv, W2, Ah);
    k_agg <<<nb_a, 256>>>(Ah, Bv, b2, 1);
    k_gemm<<<nb_g, 256>>>(Bv, W3, Ah);
    k_agg <<<nb_a, 256>>>(Ah, Bv, b3, 0);

    k_pool <<<(N_NODES + 511) / 512, 256>>>(Bv, batch);
    k_final<<<1, 640>>>(Wl, bl, (float*)d_out);
}

// round 13
// speedup vs baseline: 1.0225x; 1.0225x over previous
#include <cuda_runtime.h>

#define N_NODES 50000
#define N_EDGES 800000
#define NF 64
#define NG 64
#define NC 10
#define NBLK 196   // ceil(50000/256)
#define FIXSCALE 16777216.0f   // 2^24 fixed-point for packed degree

// ---- scratch (static __device__, no runtime allocation) ----
__device__ unsigned long long g_deg64[N_NODES];   // high32: count, low32: sum(w)*2^24
__device__ float g_dis[N_NODES];
__device__ int   g_off[N_NODES + 1];
__device__ int   g_cur[N_NODES];
__device__ int   g_bsum[256];
__device__ __align__(16) int2 g_edge[N_EDGES];     // (src_row, dis[src]*w as bits)
__device__ __align__(256) float g_A[N_NODES * NF];
__device__ __align__(256) float g_B[N_NODES * NF];
__device__ float g_pool[NG * NF];
__device__ float g_gcnt[NG];
__device__ int   g_done = 0;                       // pool completion ticket

// degree + count in ONE packed 64-bit atomic per edge
__global__ void k_deg(const int* __restrict__ col, const float* __restrict__ P) {
    int e = blockIdx.x * blockDim.x + threadIdx.x;
    if (e >= N_EDGES) return;
    float w = 1.0f / (1.0f + expf(-P[e]));
    unsigned long long pk = (1ull << 32) |
        (unsigned long long)(unsigned int)__float2uint_rn(w * FIXSCALE);
    atomicAdd(&g_deg64[col[e]], pk);
}

// ---- scan phase 1: per-block local exclusive scan of in-degree counts.
// Also zeroes pool/gcnt (folded init). ----
__global__ void k_scan1() {
    __shared__ int s[256];
    int t = threadIdx.x;
    int i = blockIdx.x * 256 + t;
    if (i < NG * NF) g_pool[i] = 0.0f;      // folded init
    if (i < NG)      g_gcnt[i] = 0.0f;
    int v = (i < N_NODES) ? (int)(g_deg64[i] >> 32) : 0;
    int val = v;
    s[t] = val;
    __syncthreads();
    #pragma unroll
    for (int d = 1; d < 256; d <<= 1) {
        int add = (t >= d) ? s[t - d] : 0;
        __syncthreads();
        val += add;
        s[t] = val;
        __syncthreads();
    }
    if (i < N_NODES) g_off[i] = val - v;    // local exclusive
    if (t == 255)    g_bsum[blockIdx.x] = val;
}

// ---- scan phase 2 (fused): each block reduces bsum[0..bid) itself, then
// adds the base to its 256 offsets and computes dis=rsqrt(deg). ----
__global__ void k_scan3() {
    __shared__ int s[256];
    int t = threadIdx.x;
    int bid = blockIdx.x;
    s[t] = (t < bid) ? g_bsum[t] : 0;       // bid <= 195 < 256
    __syncthreads();
    #pragma unroll
    for (int d = 128; d > 0; d >>= 1) {
        if (t < d) s[t] += s[t + d];
        __syncthreads();
    }
    int base = s[0];
    if (bid == 0 && t == 0) g_off[N_NODES] = N_EDGES;   // folded init
    int i = bid * 256 + t;
    if (i >= N_NODES) return;
    int o = g_off[i] + base;
    g_off[i] = o;
    g_cur[i] = o;
    float wsum = (float)(unsigned int)g_deg64[i] * (1.0f / FIXSCALE);
    g_dis[i] = rsqrtf(1.0f + wsum);         // self-loop weight 1 folded in
}

// fill CSC: per incoming edge store (source row, dis[src]*w).
// dis[col] is factored out and applied once per node in k_agg.
__global__ void k_fill(const int* __restrict__ row, const int* __restrict__ col,
                       const float* __restrict__ P) {
    int e = blockIdx.x * blockDim.x + threadIdx.x;
    if (e >= N_EDGES) return;
    int r = row[e], c = col[e];
    float w  = 1.0f / (1.0f + expf(-P[e]));
    float nm = g_dis[r] * w;                // only ONE random gather
    int slot = atomicAdd(&g_cur[c], 1);
    g_edge[slot] = make_int2(r, __float_as_int(nm));
}

// out[n,64] = in[n,64] @ W[64,64]; W column register-resident, Is broadcast LDS.128
__global__ void k_gemm(const float* __restrict__ in, const float* __restrict__ W,
                       float* __restrict__ out) {
    __shared__ float Is[4][64];
    int tx = threadIdx.x & 63;
    int ty = threadIdx.x >> 6;
    float w[64];
    #pragma unroll
    for (int k = 0; k < 64; k++) w[k] = __ldg(&W[k * 64 + tx]);
    int base = blockIdx.x * 64;
    for (int rg = 0; rg < 16; rg++) {
        int r = base + rg * 4 + ty;
        float v = (r < N_NODES) ? in[r * 64 + tx] : 0.0f;
        __syncthreads();
        Is[ty][tx] = v;
        __syncthreads();
        float a0 = 0.f, a1 = 0.f, a2 = 0.f, a3 = 0.f;
        #pragma unroll
        for (int k = 0; k < 64; k += 4) {
            float4 iv = *(const float4*)&Is[ty][k];
            a0 = fmaf(iv.x, w[k],     a0);
            a1 = fmaf(iv.y, w[k + 1], a1);
            a2 = fmaf(iv.z, w[k + 2], a2);
            a3 = fmaf(iv.w, w[k + 3], a3);
        }
        if (r < N_NODES) out[r * 64 + tx] = (a0 + a1) + (a2 + a3);
    }
}

// warp-per-node gather SpMM, float4 lanes + SOFTWARE PIPELINE (proven R8 form):
// each half-warp (16 lanes x float4 = 256B row) owns one edge of a pair;
// next iteration's 4 edge records are prefetched while the current 4 feature
// gathers are in flight. B[c] = dis_c*(dis_c*h_c + sum_e (dis_r*w_e)*h_r) + bias
__global__ void __launch_bounds__(256) k_agg(
        const float* __restrict__ A, float* __restrict__ B,
        const float* __restrict__ bias, int do_relu) {
    int node = blockIdx.x * 8 + (threadIdx.x >> 5);
    if (node >= N_NODES) return;
    int lane = threadIdx.x & 31;
    int half = lane >> 4;                 // 0 or 1: which edge of the pair
    int f    = lane & 15;                 // float4 index within the row
    const float4* __restrict__ Ar = (const float4*)A;

    float dc = g_dis[node];
    // self term: both halves add 0.5*dc*h_self (exact; halves summed later)
    float4 hs = __ldg(&Ar[node * 16 + f]);
    float hsc = 0.5f * dc;
    float ax = hsc * hs.x, ay = hsc * hs.y, az = hsc * hs.z, aw = hsc * hs.w;

    int s = g_off[node], e = g_off[node + 1];
    int i = s;
    int2 e0 = make_int2(node, 0), e1 = e0, e2 = e0, e3 = e0;
    bool have = (i + 8 <= e);
    if (have) {
        e0 = g_edge[i     + half];
        e1 = g_edge[i + 2 + half];
        e2 = g_edge[i + 4 + half];
        e3 = g_edge[i + 6 + half];
    }
    while (have) {
        float4 h0 = __ldg(&Ar[e0.x * 16 + f]);
        float4 h1 = __ldg(&Ar[e1.x * 16 + f]);
        float4 h2 = __ldg(&Ar[e2.x * 16 + f]);
        float4 h3 = __ldg(&Ar[e3.x * 16 + f]);
        float n0 = __int_as_float(e0.y), n1 = __int_as_float(e1.y);
        float n2 = __int_as_float(e2.y), n3 = __int_as_float(e3.y);
        i += 8;
        have = (i + 8 <= e);
        int2 p0 = e0, p1 = e1, p2 = e2, p3 = e3;
        if (have) {
            p0 = g_edge[i     + half];
            p1 = g_edge[i + 2 + half];
            p2 = g_edge[i + 4 + half];
            p3 = g_edge[i + 6 + half];
        }
        ax += n0 * h0.x + n1 * h1.x + n2 * h2.x + n3 * h3.x;
        ay += n0 * h0.y + n1 * h1.y + n2 * h2.y + n3 * h3.y;
        az += n0 * h0.z + n1 * h1.z + n2 * h2.z + n3 * h3.z;
        aw += n0 * h0.w + n1 * h1.w + n2 * h2.w + n3 * h3.w;
        e0 = p0; e1 = p1; e2 = p2; e3 = p3;
    }
    for (; i < e; i += 2) {               // pairwise tail; idle half contributes 0
        int idx = i + half;
        int2 ed = (idx < e) ? g_edge[idx] : make_int2(node, 0);
        float4 h = __ldg(&Ar[ed.x * 16 + f]);
        float nm = __int_as_float(ed.y);
        ax += nm * h.x; ay += nm * h.y; az += nm * h.z; aw += nm * h.w;
    }
    ax += __shfl_xor_sync(0xffffffffu, ax, 16);
    ay += __shfl_xor_sync(0xffffffffu, ay, 16);
    az += __shfl_xor_sync(0xffffffffu, az, 16);
    aw += __shfl_xor_sync(0xffffffffu, aw, 16);
    if (half == 0) {
        float4 bb = ((const float4*)bias)[f];
        float4 o;
        o.x = dc * ax + bb.x;
        o.y = dc * ay + bb.y;
        o.z = dc * az + bb.z;
        o.w = dc * aw + bb.w;
        if (do_relu) {
            o.x = fmaxf(o.x, 0.0f); o.y = fmaxf(o.y, 0.0f);
            o.z = fmaxf(o.z, 0.0f); o.w = fmaxf(o.w, 0.0f);
        }
        ((float4*)B)[node * 16 + f] = o;
    }
}

// segment mean pool + FUSED classifier epilogue (last-block ticket).
// 256 threads = 16 groups x 16 float4-lanes; each group owns a 32-node chunk.
__global__ void k_pool(const float* __restrict__ B, const int* __restrict__ batch,
                       const float* __restrict__ Wl, const float* __restrict__ bl,
                       float* __restrict__ out) {
    int t = threadIdx.x;
    int grp = t >> 4;                      // 0..15
    int f   = t & 15;                      // float4 lane
    int start = blockIdx.x * 512 + grp * 32;
    if (start < N_NODES) {
        int end = min(start + 32, N_NODES);
        const float4* __restrict__ Br = (const float4*)B;
        int cur = batch[start];
        float4 acc = make_float4(0.f, 0.f, 0.f, 0.f);
        float c = 0.0f;
        for (int i = start; i < end; i++) {
            int g = batch[i];
            if (g != cur) {
                float* p = &g_pool[cur * 64 + f * 4];
                atomicAdd(p + 0, acc.x); atomicAdd(p + 1, acc.y);
                atomicAdd(p + 2, acc.z); atomicAdd(p + 3, acc.w);
                if (f == 0) atomicAdd(&g_gcnt[cur], c);
                acc = make_float4(0.f, 0.f, 0.f, 0.f); c = 0.0f; cur = g;
            }
            float4 v = Br[i * 16 + f];
            acc.x += v.x; acc.y += v.y; acc.z += v.z; acc.w += v.w;
            c += 1.0f;
        }
        float* p = &g_pool[cur * 64 + f * 4];
        atomicAdd(p + 0, acc.x); atomicAdd(p + 1, acc.y);
        atomicAdd(p + 2, acc.z); atomicAdd(p + 3, acc.w);
        if (f == 0) atomicAdd(&g_gcnt[cur], c);
    }
    // ---- last-block ticket: final classifier ----
    __syncthreads();
    __threadfence();
    __shared__ int s_last;
    if (t == 0) {
        int old = atomicAdd(&g_done, 1);
        s_last = (old == (int)gridDim.x - 1) ? 1 : 0;
    }
    __syncthreads();
    if (s_last) {
        for (int o = t; o < NG * NC; o += 256) {
            int g = o / NC, c = o % NC;
            float cnt = fmaxf(g_gcnt[g], 1.0f);
            float sm = 0.0f;
            #pragma unroll
            for (int k = 0; k < 64; k++)
                sm += g_pool[g * 64 + k] * Wl[k * NC + c];
            out[o] = sm / cnt + bl[c];
        }
        if (t == 0) g_done = 0;            // reset for next (graph-replayed) call
    }
}

// ---------------------------------------------------------------------------
extern "C" void kernel_launch(void* const* d_in, const int* in_sizes, int n_in,
                              void* d_out, int out_size) {
    const float* x     = (const float*)d_in[0];
    const int*   ei    = (const int*)  d_in[1];   // [2, E]
    const int*   batch = (const int*)  d_in[2];
    const float* P     = (const float*)d_in[3];
    const float* W1 = (const float*)d_in[4];  const float* b1 = (const float*)d_in[5];
    const float* W2 = (const float*)d_in[6];  const float* b2 = (const float*)d_in[7];
    const float* W3 = (const float*)d_in[8];  const float* b3 = (const float*)d_in[9];
    const float* Wl = (const float*)d_in[10]; const float* bl = (const float*)d_in[11];
    const int* row = ei;
    const int* col = ei + N_EDGES;

    float *A, *Bv;
    void* degp;
    cudaGetSymbolAddress((void**)&A,  g_A);
    cudaGetSymbolAddress((void**)&Bv, g_B);
    cudaGetSymbolAddress(&degp, g_deg64);

    const int nb_e = (N_EDGES + 255) / 256;
    const int nb_g = (N_NODES + 63) / 64;
    const int nb_a = (N_NODES + 7) / 8;

    cudaMemsetAsync(degp, 0, N_NODES * sizeof(unsigned long long));
    k_deg  <<<nb_e, 256>>>(col, P);
    k_scan1<<<NBLK, 256>>>();
    k_scan3<<<NBLK, 256>>>();              // fused scan2+scan3
    k_fill <<<nb_e, 256>>>(row, col, P);

    k_gemm<<<nb_g, 256>>>(x,  W1, A);
    k_agg <<<nb_a, 256>>>(A, Bv, b1, 1);
    k_gemm<<<nb_g, 256>>>(Bv, W2, A);
    k_agg <<<nb_a, 256>>>(A, Bv, b2, 1);
    k_gemm<<<nb_g, 256>>>(Bv, W3, A);
    k_agg <<<nb_a, 256>>>(A, Bv, b3, 0);

    k_pool<<<(N_NODES + 511) / 512, 256>>>(Bv, batch, Wl, bl, (float*)d_out);
}

// round 14
// speedup vs baseline: 1.0541x; 1.0310x over previous
#include <cuda_runtime.h>

#define N_NODES 50000
#define N_EDGES 800000
#define NF 64
#define NG 64
#define NC 10
#define NBLK 196   // ceil(50000/256)
#define FIXSCALE 16777216.0f   // 2^24 fixed-point for packed degree

// ---- scratch (static __device__, no runtime allocation) ----
__device__ unsigned long long g_deg64[N_NODES];   // high32: count, low32: sum(w)*2^24
__device__ float g_dis[N_NODES];
__device__ int   g_off[N_NODES + 1];
__device__ int   g_bsum[256];
__device__ __align__(16) int2 g_rw[N_EDGES];       // (rank within target, w bits)
__device__ __align__(16) int2 g_edge[N_EDGES];     // (src_row, dis[src]*w as bits)
__device__ __align__(256) float g_A[N_NODES * NF];
__device__ __align__(256) float g_B[N_NODES * NF];
__device__ float g_pool[NG * NF];
__device__ float g_gcnt[NG];
__device__ int   g_done = 0;                       // pool completion ticket

// degree + count in ONE packed 64-bit atomic per edge; the returned old count
// is this edge's unique rank within its target -> stored for atomic-free fill.
__global__ void k_deg(const int* __restrict__ col, const float* __restrict__ P) {
    int e = blockIdx.x * blockDim.x + threadIdx.x;
    if (e >= N_EDGES) return;
    float w = 1.0f / (1.0f + expf(-P[e]));
    unsigned long long pk = (1ull << 32) |
        (unsigned long long)(unsigned int)__float2uint_rn(w * FIXSCALE);
    unsigned long long old = atomicAdd(&g_deg64[col[e]], pk);
    g_rw[e] = make_int2((int)(old >> 32), __float_as_int(w));
}

// ---- scan phase 1: per-block local exclusive scan of in-degree counts.
// Also zeroes pool/gcnt (folded init). ----
__global__ void k_scan1() {
    __shared__ int s[256];
    int t = threadIdx.x;
    int i = blockIdx.x * 256 + t;
    if (i < NG * NF) g_pool[i] = 0.0f;      // folded init
    if (i < NG)      g_gcnt[i] = 0.0f;
    int v = (i < N_NODES) ? (int)(g_deg64[i] >> 32) : 0;
    int val = v;
    s[t] = val;
    __syncthreads();
    #pragma unroll
    for (int d = 1; d < 256; d <<= 1) {
        int add = (t >= d) ? s[t - d] : 0;
        __syncthreads();
        val += add;
        s[t] = val;
        __syncthreads();
    }
    if (i < N_NODES) g_off[i] = val - v;    // local exclusive
    if (t == 255)    g_bsum[blockIdx.x] = val;
}

// ---- scan phase 2 (fused): each block reduces bsum[0..bid) itself, then
// adds the base to its 256 offsets and computes dis=rsqrt(deg). ----
__global__ void k_scan3() {
    __shared__ int s[256];
    int t = threadIdx.x;
    int bid = blockIdx.x;
    s[t] = (t < bid) ? g_bsum[t] : 0;       // bid <= 195 < 256
    __syncthreads();
    #pragma unroll
    for (int d = 128; d > 0; d >>= 1) {
        if (t < d) s[t] += s[t + d];
        __syncthreads();
    }
    int base = s[0];
    if (bid == 0 && t == 0) g_off[N_NODES] = N_EDGES;   // folded init
    int i = bid * 256 + t;
    if (i >= N_NODES) return;
    g_off[i] += base;
    float wsum = (float)(unsigned int)g_deg64[i] * (1.0f / FIXSCALE);
    g_dis[i] = rsqrtf(1.0f + wsum);         // self-loop weight 1 folded in
}

// fill CSC, ATOMIC-FREE: slot = off[target] + rank (rank captured in k_deg).
// dis[col] is factored out and applied once per node in k_agg.
__global__ void k_fill(const int* __restrict__ row, const int* __restrict__ col) {
    int e = blockIdx.x * blockDim.x + threadIdx.x;
    if (e >= N_EDGES) return;
    int r = row[e], c = col[e];
    int2 rw = g_rw[e];                      // coalesced (rank, w)
    float nm = g_dis[r] * __int_as_float(rw.y);   // one random gather
    int slot = g_off[c] + rw.x;             // plain L2 load, no atomic
    g_edge[slot] = make_int2(r, __float_as_int(nm));
}

// out[n,64] = in[n,64] @ W[64,64]; W column register-resident, Is broadcast LDS.128
__global__ void k_gemm(const float* __restrict__ in, const float* __restrict__ W,
                       float* __restrict__ out) {
    __shared__ float Is[4][64];
    int tx = threadIdx.x & 63;
    int ty = threadIdx.x >> 6;
    float w[64];
    #pragma unroll
    for (int k = 0; k < 64; k++) w[k] = __ldg(&W[k * 64 + tx]);
    int base = blockIdx.x * 64;
    for (int rg = 0; rg < 16; rg++) {
        int r = base + rg * 4 + ty;
        float v = (r < N_NODES) ? in[r * 64 + tx] : 0.0f;
        __syncthreads();
        Is[ty][tx] = v;
        __syncthreads();
        float a0 = 0.f, a1 = 0.f, a2 = 0.f, a3 = 0.f;
        #pragma unroll
        for (int k = 0; k < 64; k += 4) {
            float4 iv = *(const float4*)&Is[ty][k];
            a0 = fmaf(iv.x, w[k],     a0);
            a1 = fmaf(iv.y, w[k + 1], a1);
            a2 = fmaf(iv.z, w[k + 2], a2);
            a3 = fmaf(iv.w, w[k + 3], a3);
        }
        if (r < N_NODES) out[r * 64 + tx] = (a0 + a1) + (a2 + a3);
    }
}

// warp-per-node gather SpMM, float4 lanes + SOFTWARE PIPELINE (proven R8 form).
__global__ void __launch_bounds__(256) k_agg(
        const float* __restrict__ A, float* __restrict__ B,
        const float* __restrict__ bias, int do_relu) {
    int node = blockIdx.x * 8 + (threadIdx.x >> 5);
    if (node >= N_NODES) return;
    int lane = threadIdx.x & 31;
    int half = lane >> 4;                 // 0 or 1: which edge of the pair
    int f    = lane & 15;                 // float4 index within the row
    const float4* __restrict__ Ar = (const float4*)A;

    float dc = g_dis[node];
    float4 hs = __ldg(&Ar[node * 16 + f]);
    float hsc = 0.5f * dc;
    float ax = hsc * hs.x, ay = hsc * hs.y, az = hsc * hs.z, aw = hsc * hs.w;

    int s = g_off[node], e = g_off[node + 1];
    int i = s;
    int2 e0 = make_int2(node, 0), e1 = e0, e2 = e0, e3 = e0;
    bool have = (i + 8 <= e);
    if (have) {
        e0 = g_edge[i     + half];
        e1 = g_edge[i + 2 + half];
        e2 = g_edge[i + 4 + half];
        e3 = g_edge[i + 6 + half];
    }
    while (have) {
        float4 h0 = __ldg(&Ar[e0.x * 16 + f]);
        float4 h1 = __ldg(&Ar[e1.x * 16 + f]);
        float4 h2 = __ldg(&Ar[e2.x * 16 + f]);
        float4 h3 = __ldg(&Ar[e3.x * 16 + f]);
        float n0 = __int_as_float(e0.y), n1 = __int_as_float(e1.y);
        float n2 = __int_as_float(e2.y), n3 = __int_as_float(e3.y);
        i += 8;
        have = (i + 8 <= e);
        int2 p0 = e0, p1 = e1, p2 = e2, p3 = e3;
        if (have) {
            p0 = g_edge[i     + half];
            p1 = g_edge[i + 2 + half];
            p2 = g_edge[i + 4 + half];
            p3 = g_edge[i + 6 + half];
        }
        ax += n0 * h0.x + n1 * h1.x + n2 * h2.x + n3 * h3.x;
        ay += n0 * h0.y + n1 * h1.y + n2 * h2.y + n3 * h3.y;
        az += n0 * h0.z + n1 * h1.z + n2 * h2.z + n3 * h3.z;
        aw += n0 * h0.w + n1 * h1.w + n2 * h2.w + n3 * h3.w;
        e0 = p0; e1 = p1; e2 = p2; e3 = p3;
    }
    for (; i < e; i += 2) {               // pairwise tail; idle half contributes 0
        int idx = i + half;
        int2 ed = (idx < e) ? g_edge[idx] : make_int2(node, 0);
        float4 h = __ldg(&Ar[ed.x * 16 + f]);
        float nm = __int_as_float(ed.y);
        ax += nm * h.x; ay += nm * h.y; az += nm * h.z; aw += nm * h.w;
    }
    ax += __shfl_xor_sync(0xffffffffu, ax, 16);
    ay += __shfl_xor_sync(0xffffffffu, ay, 16);
    az += __shfl_xor_sync(0xffffffffu, az, 16);
    aw += __shfl_xor_sync(0xffffffffu, aw, 16);
    if (half == 0) {
        float4 bb = ((const float4*)bias)[f];
        float4 o;
        o.x = dc * ax + bb.x;
        o.y = dc * ay + bb.y;
        o.z = dc * az + bb.z;
        o.w = dc * aw + bb.w;
        if (do_relu) {
            o.x = fmaxf(o.x, 0.0f); o.y = fmaxf(o.y, 0.0f);
            o.z = fmaxf(o.z, 0.0f); o.w = fmaxf(o.w, 0.0f);
        }
        ((float4*)B)[node * 16 + f] = o;
    }
}

// segment mean pool + FUSED classifier epilogue (last-block ticket).
__global__ void k_pool(const float* __restrict__ B, const int* __restrict__ batch,
                       const float* __restrict__ Wl, const float* __restrict__ bl,
                       float* __restrict__ out) {
    int t = threadIdx.x;
    int grp = t >> 4;                      // 0..15
    int f   = t & 15;                      // float4 lane
    int start = blockIdx.x * 512 + grp * 32;
    if (start < N_NODES) {
        int end = min(start + 32, N_NODES);
        const float4* __restrict__ Br = (const float4*)B;
        int cur = batch[start];
        float4 acc = make_float4(0.f, 0.f, 0.f, 0.f);
        float c = 0.0f;
        for (int i = start; i < end; i++) {
            int g = batch[i];
            if (g != cur) {
                float* p = &g_pool[cur * 64 + f * 4];
                atomicAdd(p + 0, acc.x); atomicAdd(p + 1, acc.y);
                atomicAdd(p + 2, acc.z); atomicAdd(p + 3, acc.w);
                if (f == 0) atomicAdd(&g_gcnt[cur], c);
                acc = make_float4(0.f, 0.f, 0.f, 0.f); c = 0.0f; cur = g;
            }
            float4 v = Br[i * 16 + f];
            acc.x += v.x; acc.y += v.y; acc.z += v.z; acc.w += v.w;
            c += 1.0f;
        }
        float* p = &g_pool[cur * 64 + f * 4];
        atomicAdd(p + 0, acc.x); atomicAdd(p + 1, acc.y);
        atomicAdd(p + 2, acc.z); atomicAdd(p + 3, acc.w);
        if (f == 0) atomicAdd(&g_gcnt[cur], c);
    }
    __syncthreads();
    __threadfence();
    __shared__ int s_last;
    if (t == 0) {
        int old = atomicAdd(&g_done, 1);
        s_last = (old == (int)gridDim.x - 1) ? 1 : 0;
    }
    __syncthreads();
    if (s_last) {
        for (int o = t; o < NG * NC; o += 256) {
            int g = o / NC, c = o % NC;
            float cnt = fmaxf(g_gcnt[g], 1.0f);
            float sm = 0.0f;
            #pragma unroll
            for (int k = 0; k < 64; k++)
                sm += g_pool[g * 64 + k] * Wl[k * NC + c];
            out[o] = sm / cnt + bl[c];
        }
        if (t == 0) g_done = 0;            // reset for next (graph-replayed) call
    }
}

// ---------------------------------------------------------------------------
extern "C" void kernel_launch(void* const* d_in, const int* in_sizes, int n_in,
                              void* d_out, int out_size) {
    const float* x     = (const float*)d_in[0];
    const int*   ei    = (const int*)  d_in[1];   // [2, E]
    const int*   batch = (const int*)  d_in[2];
    const float* P     = (const float*)d_in[3];
    const float* W1 = (const float*)d_in[4];  const float* b1 = (const float*)d_in[5];
    const float* W2 = (const float*)d_in[6];  const float* b2 = (const float*)d_in[7];
    const float* W3 = (const float*)d_in[8];  const float* b3 = (const float*)d_in[9];
    const float* Wl = (const float*)d_in[10]; const float* bl = (const float*)d_in[11];
    const int* row = ei;
    const int* col = ei + N_EDGES;

    float *A, *Bv;
    void* degp;
    cudaGetSymbolAddress((void**)&A,  g_A);
    cudaGetSymbolAddress((void**)&Bv, g_B);
    cudaGetSymbolAddress(&degp, g_deg64);

    const int nb_e = (N_EDGES + 255) / 256;
    const int nb_g = (N_NODES + 63) / 64;
    const int nb_a = (N_NODES + 7) / 8;

    // fork: gemm1 (inputs-only) runs concurrently with the preprocessing chain
    cudaStream_t s2;
    cudaStreamCreateWithFlags(&s2, cudaStreamNonBlocking);
    cudaEvent_t evFork, evJoin;
    cudaEventCreateWithFlags(&evFork, cudaEventDisableTiming);
    cudaEventCreateWithFlags(&evJoin, cudaEventDisableTiming);

    cudaEventRecord(evFork, 0);
    cudaStreamWaitEvent(s2, evFork, 0);
    k_gemm<<<nb_g, 256, 0, s2>>>(x, W1, A);
    cudaEventRecord(evJoin, s2);

    cudaMemsetAsync(degp, 0, N_NODES * sizeof(unsigned long long));
    k_deg  <<<nb_e, 256>>>(col, P);
    k_scan1<<<NBLK, 256>>>();
    k_scan3<<<NBLK, 256>>>();              // fused scan2+scan3
    k_fill <<<nb_e, 256>>>(row, col);      // atomic-free

    cudaStreamWaitEvent(0, evJoin, 0);     // join gemm1 branch

    k_agg <<<nb_a, 256>>>(A, Bv, b1, 1);
    k_gemm<<<nb_g, 256>>>(Bv, W2, A);
    k_agg <<<nb_a, 256>>>(A, Bv, b2, 1);
    k_gemm<<<nb_g, 256>>>(Bv, W3, A);
    k_agg <<<nb_a, 256>>>(A, Bv, b3, 0);

    k_pool<<<(N_NODES + 511) / 512, 256>>>(Bv, batch, Wl, bl, (float*)d_out);

    cudaEventDestroy(evFork);
    cudaEventDestroy(evJoin);
    cudaStreamDestroy(s2);
}